// round 3
// baseline (speedup 1.0000x reference)
#include <cuda_runtime.h>
#include <cuda_bf16.h>

// CenterLoss: loss = mean_b sum_d (features[b,d] - centers[labels[b],d])^2
// B=65536, D=256, C=100000. HBM-bound gather + reduction.
// Single-kernel fence-reduction: last CTA to finish sums all partials
// in a fixed order (deterministic) and resets the counter for graph replay.

#define BATCH    65536
#define FEAT_DIM 256
#define GRID1    1184          // 8 CTAs/SM * 148 SMs
#define BLOCK1   256           // 8 warps per CTA

__device__ float g_partials[GRID1];
__device__ unsigned int g_count = 0;

__global__ __launch_bounds__(BLOCK1) void center_loss_fused(
    const float* __restrict__ features,
    const int*   __restrict__ labels,
    const float* __restrict__ centers,
    float*       __restrict__ out)
{
    const int lane   = threadIdx.x & 31;
    const int wid    = threadIdx.x >> 5;
    const int warp_g = (blockIdx.x * BLOCK1 + threadIdx.x) >> 5;
    const int nwarps = (GRID1 * BLOCK1) >> 5;

    float acc = 0.0f;

    for (int row = warp_g; row < BATCH; row += nwarps) {
        const int lbl = labels[row];
        const float4* __restrict__ f =
            reinterpret_cast<const float4*>(features + (size_t)row * FEAT_DIM);
        const float4* __restrict__ c =
            reinterpret_cast<const float4*>(centers + (size_t)lbl * FEAT_DIM);

        // 256 floats per row = 64 float4; 32 lanes * 2 float4 each.
        float4 f0 = f[lane];
        float4 f1 = f[lane + 32];
        float4 c0 = c[lane];
        float4 c1 = c[lane + 32];

        float d;
        d = f0.x - c0.x; acc = fmaf(d, d, acc);
        d = f0.y - c0.y; acc = fmaf(d, d, acc);
        d = f0.z - c0.z; acc = fmaf(d, d, acc);
        d = f0.w - c0.w; acc = fmaf(d, d, acc);
        d = f1.x - c1.x; acc = fmaf(d, d, acc);
        d = f1.y - c1.y; acc = fmaf(d, d, acc);
        d = f1.z - c1.z; acc = fmaf(d, d, acc);
        d = f1.w - c1.w; acc = fmaf(d, d, acc);
    }

    // ---- intra-CTA reduction ----
    #pragma unroll
    for (int o = 16; o > 0; o >>= 1)
        acc += __shfl_xor_sync(0xFFFFFFFFu, acc, o);

    __shared__ float smem[BLOCK1 / 32];
    if (lane == 0) smem[wid] = acc;
    __syncthreads();

    __shared__ bool is_last;
    if (threadIdx.x == 0) {
        float v = 0.0f;
        #pragma unroll
        for (int i = 0; i < BLOCK1 / 32; i++) v += smem[i];
        g_partials[blockIdx.x] = v;
        __threadfence();
        unsigned int prev = atomicAdd(&g_count, 1u);
        is_last = (prev == GRID1 - 1);
    }
    __syncthreads();

    // ---- last CTA: deterministic fixed-order final reduction ----
    if (is_last) {
        const int tid = threadIdx.x;
        float v = 0.0f;
        // fixed strided order: deterministic across replays
        for (int i = tid; i < GRID1; i += BLOCK1)
            v += g_partials[i];

        #pragma unroll
        for (int o = 16; o > 0; o >>= 1)
            v += __shfl_xor_sync(0xFFFFFFFFu, v, o);

        __shared__ float smem2[BLOCK1 / 32];
        if (lane == 0) smem2[wid] = v;
        __syncthreads();

        if (threadIdx.x == 0) {
            float t = 0.0f;
            #pragma unroll
            for (int i = 0; i < BLOCK1 / 32; i++) t += smem2[i];
            out[0] = t * (1.0f / (float)BATCH);   // LAMBDA_C = 1.0
            g_count = 0;                          // reset for next graph replay
            __threadfence();
        }
    }
}

extern "C" void kernel_launch(void* const* d_in, const int* in_sizes, int n_in,
                              void* d_out, int out_size)
{
    const float* features = (const float*)d_in[0];
    const int*   labels   = (const int*)  d_in[1];
    const float* centers  = (const float*)d_in[2];
    float*       out      = (float*)d_out;

    center_loss_fused<<<GRID1, BLOCK1>>>(features, labels, centers, out);
}

// round 4
// speedup vs baseline: 1.2790x; 1.2790x over previous
#include <cuda_runtime.h>
#include <cuda_bf16.h>

// CenterLoss: loss = mean_b sum_d (features[b,d] - centers[labels[b],d])^2
// B=65536, D=256, C=100000. HBM-bound gather + reduction.
// Two-kernel split (stage1 at HBM roofline) + PDL to hide stage2 launch latency.

#define BATCH    65536
#define FEAT_DIM 256
#define GRID1    1184          // 8 CTAs/SM * 148 SMs
#define BLOCK1   256           // 8 warps per CTA

__device__ float g_partials[GRID1];

__global__ __launch_bounds__(BLOCK1) void center_loss_stage1(
    const float* __restrict__ features,
    const int*   __restrict__ labels,
    const float* __restrict__ centers)
{
    const int lane   = threadIdx.x & 31;
    const int wid    = threadIdx.x >> 5;
    const int warp_g = (blockIdx.x * BLOCK1 + threadIdx.x) >> 5;
    const int nwarps = (GRID1 * BLOCK1) >> 5;

    float acc = 0.0f;

    for (int row = warp_g; row < BATCH; row += nwarps) {
        const int lbl = labels[row];
        const float4* __restrict__ f =
            reinterpret_cast<const float4*>(features + (size_t)row * FEAT_DIM);
        const float4* __restrict__ c =
            reinterpret_cast<const float4*>(centers + (size_t)lbl * FEAT_DIM);

        // 256 floats per row = 64 float4; 32 lanes * 2 float4 each.
        float4 f0 = f[lane];
        float4 f1 = f[lane + 32];
        float4 c0 = c[lane];
        float4 c1 = c[lane + 32];

        float d;
        d = f0.x - c0.x; acc = fmaf(d, d, acc);
        d = f0.y - c0.y; acc = fmaf(d, d, acc);
        d = f0.z - c0.z; acc = fmaf(d, d, acc);
        d = f0.w - c0.w; acc = fmaf(d, d, acc);
        d = f1.x - c1.x; acc = fmaf(d, d, acc);
        d = f1.y - c1.y; acc = fmaf(d, d, acc);
        d = f1.z - c1.z; acc = fmaf(d, d, acc);
        d = f1.w - c1.w; acc = fmaf(d, d, acc);
    }

    // warp reduce
    #pragma unroll
    for (int o = 16; o > 0; o >>= 1)
        acc += __shfl_xor_sync(0xFFFFFFFFu, acc, o);

    __shared__ float smem[BLOCK1 / 32];
    if (lane == 0) smem[wid] = acc;
    __syncthreads();

    if (threadIdx.x == 0) {
        float v = 0.0f;
        #pragma unroll
        for (int i = 0; i < BLOCK1 / 32; i++) v += smem[i];
        g_partials[blockIdx.x] = v;
        // make the partial visible before allowing the dependent grid to run
        __threadfence();
    }
    __syncthreads();

    // All CTAs trigger after their fenced partial write; the PDL-dependent
    // stage2 launch fires once every CTA has triggered.
    cudaTriggerProgrammaticLaunchCompletion();
}

__global__ __launch_bounds__(1024) void center_loss_stage2(float* __restrict__ out)
{
    // Prologue overlaps stage1 drain; wait for all stage1 triggers before reading.
    cudaGridDependencySynchronize();

    const int tid = threadIdx.x;
    float acc = 0.0f;
    for (int i = tid; i < GRID1; i += 1024)
        acc += g_partials[i];

    #pragma unroll
    for (int o = 16; o > 0; o >>= 1)
        acc += __shfl_xor_sync(0xFFFFFFFFu, acc, o);

    __shared__ float smem[32];
    if ((tid & 31) == 0) smem[tid >> 5] = acc;
    __syncthreads();

    if (tid < 32) {
        float v = smem[tid];
        #pragma unroll
        for (int o = 16; o > 0; o >>= 1)
            v += __shfl_xor_sync(0xFFFFFFFFu, v, o);
        if (tid == 0)
            out[0] = v * (1.0f / (float)BATCH);   // LAMBDA_C = 1.0
    }
}

extern "C" void kernel_launch(void* const* d_in, const int* in_sizes, int n_in,
                              void* d_out, int out_size)
{
    const float* features = (const float*)d_in[0];
    const int*   labels   = (const int*)  d_in[1];
    const float* centers  = (const float*)d_in[2];
    float*       out      = (float*)d_out;

    center_loss_stage1<<<GRID1, BLOCK1>>>(features, labels, centers);

    // Stage2 with programmatic dependent launch: overlaps its launch/prologue
    // with stage1's drain phase.
    cudaLaunchAttribute attrs[1];
    attrs[0].id = cudaLaunchAttributeProgrammaticStreamSerialization;
    attrs[0].val.programmaticStreamSerializationAllowed = 1;

    cudaLaunchConfig_t cfg = {};
    cfg.gridDim  = dim3(1, 1, 1);
    cfg.blockDim = dim3(1024, 1, 1);
    cfg.dynamicSmemBytes = 0;
    cfg.stream   = 0;
    cfg.attrs    = attrs;
    cfg.numAttrs = 1;

    cudaLaunchKernelEx(&cfg, center_loss_stage2, out);
}

// round 5
// speedup vs baseline: 1.5920x; 1.2448x over previous
#include <cuda_runtime.h>
#include <cuda_bf16.h>

// CenterLoss: loss = mean_b sum_d (features[b,d] - centers[labels[b],d])^2
// B=65536, D=256, C=100000. HBM-bound gather + reduction.
// Stage1: streaming hints (__ldcs) on features/labels so gathered center rows
// stay L2-resident for repeat labels; label load software-pipelined.
// Stage2: tiny final reduce, PDL-overlapped with stage1 drain.

#define BATCH    65536
#define FEAT_DIM 256
#define GRID1    1184          // 8 CTAs/SM * 148 SMs
#define BLOCK1   256           // 8 warps per CTA

__device__ float g_partials[GRID1];

__global__ __launch_bounds__(BLOCK1) void center_loss_stage1(
    const float* __restrict__ features,
    const int*   __restrict__ labels,
    const float* __restrict__ centers)
{
    const int lane   = threadIdx.x & 31;
    const int wid    = threadIdx.x >> 5;
    const int warp_g = (blockIdx.x * BLOCK1 + threadIdx.x) >> 5;
    const int nwarps = (GRID1 * BLOCK1) >> 5;

    float acc = 0.0f;

    int row = warp_g;
    int lbl = (row < BATCH) ? __ldcs(labels + row) : 0;   // pipelined label

    for (; row < BATCH; ) {
        const int next_row = row + nwarps;
        // prefetch next label early — breaks label->address->load serial chain
        const int next_lbl = (next_row < BATCH) ? __ldcs(labels + next_row) : 0;

        const float4* __restrict__ f =
            reinterpret_cast<const float4*>(features + (size_t)row * FEAT_DIM);
        const float4* __restrict__ c =
            reinterpret_cast<const float4*>(centers + (size_t)lbl * FEAT_DIM);

        // 256 floats per row = 64 float4; 32 lanes * 2 float4 each.
        // features: streaming (no reuse, keep them out of L2's way)
        float4 f0 = __ldcs(f + lane);
        float4 f1 = __ldcs(f + lane + 32);
        // centers: default caching (repeat labels hit L2)
        float4 c0 = __ldg(c + lane);
        float4 c1 = __ldg(c + lane + 32);

        float d;
        d = f0.x - c0.x; acc = fmaf(d, d, acc);
        d = f0.y - c0.y; acc = fmaf(d, d, acc);
        d = f0.z - c0.z; acc = fmaf(d, d, acc);
        d = f0.w - c0.w; acc = fmaf(d, d, acc);
        d = f1.x - c1.x; acc = fmaf(d, d, acc);
        d = f1.y - c1.y; acc = fmaf(d, d, acc);
        d = f1.z - c1.z; acc = fmaf(d, d, acc);
        d = f1.w - c1.w; acc = fmaf(d, d, acc);

        row = next_row;
        lbl = next_lbl;
    }

    // warp reduce
    #pragma unroll
    for (int o = 16; o > 0; o >>= 1)
        acc += __shfl_xor_sync(0xFFFFFFFFu, acc, o);

    __shared__ float smem[BLOCK1 / 32];
    if (lane == 0) smem[wid] = acc;
    __syncthreads();

    if (threadIdx.x == 0) {
        float v = 0.0f;
        #pragma unroll
        for (int i = 0; i < BLOCK1 / 32; i++) v += smem[i];
        g_partials[blockIdx.x] = v;
        __threadfence();   // partial visible before dependent grid reads it
    }
    __syncthreads();

    cudaTriggerProgrammaticLaunchCompletion();
}

__global__ __launch_bounds__(1024) void center_loss_stage2(float* __restrict__ out)
{
    cudaGridDependencySynchronize();

    const int tid = threadIdx.x;
    float acc = 0.0f;
    for (int i = tid; i < GRID1; i += 1024)
        acc += g_partials[i];

    #pragma unroll
    for (int o = 16; o > 0; o >>= 1)
        acc += __shfl_xor_sync(0xFFFFFFFFu, acc, o);

    __shared__ float smem[32];
    if ((tid & 31) == 0) smem[tid >> 5] = acc;
    __syncthreads();

    if (tid < 32) {
        float v = smem[tid];
        #pragma unroll
        for (int o = 16; o > 0; o >>= 1)
            v += __shfl_xor_sync(0xFFFFFFFFu, v, o);
        if (tid == 0)
            out[0] = v * (1.0f / (float)BATCH);   // LAMBDA_C = 1.0
    }
}

extern "C" void kernel_launch(void* const* d_in, const int* in_sizes, int n_in,
                              void* d_out, int out_size)
{
    const float* features = (const float*)d_in[0];
    const int*   labels   = (const int*)  d_in[1];
    const float* centers  = (const float*)d_in[2];
    float*       out      = (float*)d_out;

    center_loss_stage1<<<GRID1, BLOCK1>>>(features, labels, centers);

    cudaLaunchAttribute attrs[1];
    attrs[0].id = cudaLaunchAttributeProgrammaticStreamSerialization;
    attrs[0].val.programmaticStreamSerializationAllowed = 1;

    cudaLaunchConfig_t cfg = {};
    cfg.gridDim  = dim3(1, 1, 1);
    cfg.blockDim = dim3(1024, 1, 1);
    cfg.dynamicSmemBytes = 0;
    cfg.stream   = 0;
    cfg.attrs    = attrs;
    cfg.numAttrs = 1;

    cudaLaunchKernelEx(&cfg, center_loss_stage2, out);
}